// round 1
// baseline (speedup 1.0000x reference)
#include <cuda_runtime.h>
#include <cuda_bf16.h>
#include <math.h>

// Problem constants (from reference)
#define NN 100000
#define DD 128
#define AA 4096
#define SS 512
// 1/TEMP = 10

// Scratch: per-row inverse norm + per-anchor loss (no device mallocs allowed)
__device__ float g_invnorm[NN];
__device__ float g_aloss[AA];

// ---------------------------------------------------------------------------
// Kernel 1: invnorm[i] = rsqrt(sum_d x[i][d]^2).  One warp per row.
// Lane l reads float4 at offset l -> 32 lanes * 16B = 512B coalesced per row.
// ---------------------------------------------------------------------------
__global__ void norm_kernel(const float* __restrict__ x) {
    int gwarp = (blockIdx.x * blockDim.x + threadIdx.x) >> 5;
    int lane  = threadIdx.x & 31;
    if (gwarp >= NN) return;
    const float4* row = reinterpret_cast<const float4*>(x + (size_t)gwarp * DD);
    float4 v = row[lane];
    float s = v.x * v.x + v.y * v.y + v.z * v.z + v.w * v.w;
#pragma unroll
    for (int o = 16; o; o >>= 1) s += __shfl_xor_sync(0xFFFFFFFFu, s, o);
    if (lane == 0) g_invnorm[gwarp] = rsqrtf(s);
}

// ---------------------------------------------------------------------------
// Kernel 2: one block (8 warps, 256 thr) per anchor.
// Anchor feature lives in registers (1 float4 per lane), pre-scaled by its
// inverse norm. Each warp strides over the 512 samples.
// ---------------------------------------------------------------------------
__global__ __launch_bounds__(256) void loss_kernel(
    const float* __restrict__ x, const int* __restrict__ y,
    const int* __restrict__ anchors, const int* __restrict__ sampled)
{
    int a    = blockIdx.x;
    int lane = threadIdx.x & 31;
    int warp = threadIdx.x >> 5;   // 0..7

    int   ai   = anchors[a];
    float inva = g_invnorm[ai];
    int   ay   = y[ai];

    float4 av = reinterpret_cast<const float4*>(x + (size_t)ai * DD)[lane];
    av.x *= inva; av.y *= inva; av.z *= inva; av.w *= inva;

    const int* __restrict__ srow = sampled + (size_t)a * SS;

    float num = 0.0f, den = 0.0f, cnt = 0.0f;

    for (int s = warp; s < SS; s += 8) {
        int si = srow[s];                                   // warp-uniform broadcast load
        float4 sv = reinterpret_cast<const float4*>(x + (size_t)si * DD)[lane];
        float d = av.x * sv.x + av.y * sv.y + av.z * sv.z + av.w * sv.w;
#pragma unroll
        for (int o = 16; o; o >>= 1) d += __shfl_xor_sync(0xFFFFFFFFu, d, o);
        float sim = d * g_invnorm[si];
        float e   = expf(sim * 10.0f);                      // exp(sim / TEMP)
        den += e;
        if (y[si] == ay) { num += e; cnt += 1.0f; }
    }

    // num/den/cnt are identical across lanes of a warp (post-reduce e is uniform)
    __shared__ float s_num[8], s_den[8], s_cnt[8];
    if (lane == 0) { s_num[warp] = num; s_den[warp] = den; s_cnt[warp] = cnt; }
    __syncthreads();

    if (threadIdx.x == 0) {
        float nm = 0.0f, dn = 0.0f, c = 0.0f;
#pragma unroll
        for (int w = 0; w < 8; w++) { nm += s_num[w]; dn += s_den[w]; c += s_cnt[w]; }
        float loss = 0.0f;
        if (c > 0.0f) loss = (logf(dn) - logf(nm)) / c;     // -log(num/den)/cnt
        g_aloss[a] = loss;
    }
}

// ---------------------------------------------------------------------------
// Kernel 3: deterministic reduction of the 4096 per-anchor losses.
// ---------------------------------------------------------------------------
__global__ void reduce_kernel(float* __restrict__ out) {
    __shared__ float sh[256];
    float s = 0.0f;
    for (int i = threadIdx.x; i < AA; i += 256) s += g_aloss[i];
    sh[threadIdx.x] = s;
    __syncthreads();
    for (int o = 128; o; o >>= 1) {
        if (threadIdx.x < o) sh[threadIdx.x] += sh[threadIdx.x + o];
        __syncthreads();
    }
    if (threadIdx.x == 0) out[0] = sh[0];
}

extern "C" void kernel_launch(void* const* d_in, const int* in_sizes, int n_in,
                              void* d_out, int out_size) {
    const float* x       = (const float*)d_in[0];
    const int*   y       = (const int*)  d_in[1];
    const int*   anchors = (const int*)  d_in[2];
    const int*   sampled = (const int*)  d_in[3];
    float*       out     = (float*)d_out;

    (void)in_sizes; (void)n_in; (void)out_size;

    // 1 warp/row -> 8 rows per 256-thread block
    norm_kernel<<<(NN + 7) / 8, 256>>>(x);
    loss_kernel<<<AA, 256>>>(x, y, anchors, sampled);
    reduce_kernel<<<1, 256>>>(out);
}

// round 2
// speedup vs baseline: 1.2883x; 1.2883x over previous
#include <cuda_runtime.h>
#include <cuda_fp16.h>
#include <math.h>

#define NN 100000
#define DD 128
#define AA 4096
#define SS 512
// 1/TEMP = 10

// Scratch (no device mallocs allowed): normalized fp16 features + per-anchor loss
__device__ __half g_xh[(size_t)NN * DD];   // 25.6 MB
__device__ float  g_aloss[AA];

// ---------------------------------------------------------------------------
// Kernel 1: fused normalize + fp16 convert. One warp per row.
// Lane l holds float4 (4 elems) of the row; reduce ||x||, scale, store 8 B.
// ---------------------------------------------------------------------------
__global__ void norm_convert_kernel(const float* __restrict__ x) {
    int row  = (blockIdx.x * blockDim.x + threadIdx.x) >> 5;
    int lane = threadIdx.x & 31;
    if (row >= NN) return;
    float4 v = reinterpret_cast<const float4*>(x + (size_t)row * DD)[lane];
    float s = v.x * v.x + v.y * v.y + v.z * v.z + v.w * v.w;
#pragma unroll
    for (int o = 16; o; o >>= 1) s += __shfl_xor_sync(0xFFFFFFFFu, s, o);
    float inv = rsqrtf(s);
    __half2 h[2];
    h[0] = __floats2half2_rn(v.x * inv, v.y * inv);
    h[1] = __floats2half2_rn(v.z * inv, v.w * inv);
    reinterpret_cast<uint2*>(g_xh + (size_t)row * DD)[lane] =
        *reinterpret_cast<uint2*>(h);
}

// ---------------------------------------------------------------------------
// Kernel 2: one block (8 warps) per anchor. Half-warp per sample:
// 16 lanes x float4(=8 halves) = 256 B coalesced per sample row.
// ---------------------------------------------------------------------------
__global__ __launch_bounds__(256) void loss_kernel(
    const int* __restrict__ y,
    const int* __restrict__ anchors,
    const int* __restrict__ sampled)
{
    __shared__ int   s_idx[SS];
    __shared__ float s_num[16], s_den[16], s_cnt[16];

    int a    = blockIdx.x;
    int tid  = threadIdx.x;
    int lane = tid & 31;
    int warp = tid >> 5;     // 0..7
    int hw   = lane >> 4;    // half-warp id within warp (0/1)
    int hl   = lane & 15;    // lane within half-warp

    // Stage sample indices
    for (int i = tid; i < SS; i += 256) s_idx[i] = sampled[(size_t)a * SS + i];

    int ai = anchors[a];
    int ay = y[ai];

    // Anchor row: 8 fp16 values per half-lane -> 8 fp32 registers
    float4 araw = reinterpret_cast<const float4*>(g_xh + (size_t)ai * DD)[hl];
    const __half2* ah = reinterpret_cast<const __half2*>(&araw);
    float af[8];
#pragma unroll
    for (int j = 0; j < 4; j++) {
        float2 f = __half22float2(ah[j]);
        af[2 * j]     = f.x;
        af[2 * j + 1] = f.y;
    }
    __syncthreads();

    float num = 0.0f, den = 0.0f, cnt = 0.0f;

#pragma unroll 4
    for (int s = warp * 2 + hw; s < SS; s += 16) {
        int si = s_idx[s];
        float4 sraw = reinterpret_cast<const float4*>(g_xh + (size_t)si * DD)[hl];
        const __half2* sh = reinterpret_cast<const __half2*>(&sraw);
        float d = 0.0f;
#pragma unroll
        for (int j = 0; j < 4; j++) {
            float2 f = __half22float2(sh[j]);
            d = fmaf(af[2 * j],     f.x, d);
            d = fmaf(af[2 * j + 1], f.y, d);
        }
        // 16-lane reduce (xor offsets < 16 stay within the half-warp)
#pragma unroll
        for (int o = 8; o; o >>= 1) d += __shfl_xor_sync(0xFFFFFFFFu, d, o);
        float e = __expf(d * 10.0f);
        den += e;
        if (y[si] == ay) { num += e; cnt += 1.0f; }
    }

    // Sums are uniform within each half-warp
    if (hl == 0) {
        int slot = warp * 2 + hw;
        s_num[slot] = num; s_den[slot] = den; s_cnt[slot] = cnt;
    }
    __syncthreads();

    if (tid == 0) {
        float nm = 0.0f, dn = 0.0f, c = 0.0f;
#pragma unroll
        for (int k = 0; k < 16; k++) { nm += s_num[k]; dn += s_den[k]; c += s_cnt[k]; }
        float loss = 0.0f;
        if (c > 0.0f) loss = (logf(dn) - logf(nm)) / c;  // -log(num/den)/cnt
        g_aloss[a] = loss;
    }
}

// ---------------------------------------------------------------------------
// Kernel 3: deterministic reduction of per-anchor losses.
// ---------------------------------------------------------------------------
__global__ void reduce_kernel(float* __restrict__ out) {
    __shared__ float sh[256];
    float s = 0.0f;
    for (int i = threadIdx.x; i < AA; i += 256) s += g_aloss[i];
    sh[threadIdx.x] = s;
    __syncthreads();
    for (int o = 128; o; o >>= 1) {
        if (threadIdx.x < o) sh[threadIdx.x] += sh[threadIdx.x + o];
        __syncthreads();
    }
    if (threadIdx.x == 0) out[0] = sh[0];
}

extern "C" void kernel_launch(void* const* d_in, const int* in_sizes, int n_in,
                              void* d_out, int out_size) {
    const float* x       = (const float*)d_in[0];
    const int*   y       = (const int*)  d_in[1];
    const int*   anchors = (const int*)  d_in[2];
    const int*   sampled = (const int*)  d_in[3];
    float*       out     = (float*)d_out;

    (void)in_sizes; (void)n_in; (void)out_size; (void)x;

    norm_convert_kernel<<<(NN + 7) / 8, 256>>>(x);
    loss_kernel<<<AA, 256>>>(y, anchors, sampled);
    reduce_kernel<<<1, 256>>>(out);
}

// round 6
// speedup vs baseline: 2.1713x; 1.6854x over previous
#include <cuda_runtime.h>
#include <cuda_fp16.h>
#include <math.h>

#define NN 100000
#define DD 128
#define AA 4096
#define SS 512
// 1/TEMP = 10

// Scratch (no device mallocs allowed)
__device__ __half g_xh[(size_t)NN * DD];   // normalized fp16 features, 25.6 MB
__device__ float  g_aloss[AA];

// ---------------------------------------------------------------------------
// Kernel 1: fused normalize + fp16 convert. One warp per row.
// ---------------------------------------------------------------------------
__global__ void norm_convert_kernel(const float* __restrict__ x) {
    int row  = (blockIdx.x * blockDim.x + threadIdx.x) >> 5;
    int lane = threadIdx.x & 31;
    if (row >= NN) return;
    float4 v = reinterpret_cast<const float4*>(x + (size_t)row * DD)[lane];
    float s = v.x * v.x + v.y * v.y + v.z * v.z + v.w * v.w;
#pragma unroll
    for (int o = 16; o; o >>= 1) s += __shfl_xor_sync(0xFFFFFFFFu, s, o);
    float inv = rsqrtf(s);
    __half2 h[2];
    h[0] = __floats2half2_rn(v.x * inv, v.y * inv);
    h[1] = __floats2half2_rn(v.z * inv, v.w * inv);
    reinterpret_cast<uint2*>(g_xh + (size_t)row * DD)[lane] =
        *reinterpret_cast<uint2*>(h);
}

// ---------------------------------------------------------------------------
// Kernel 2: one block (8 warps) per anchor. Half-warp per sample:
// each half-lane owns float4 = 16 B = 8 fp16 -> 16 lanes x 16 B = full 256 B
// row, coalesced. 3-deep software-pipelined prefetch ring keeps 3 LDGs in
// flight per half-warp, hiding ~250-cycle L2 latency behind the
// convert/FMA/shuffle/exp chain of earlier samples.
// ---------------------------------------------------------------------------
__global__ __launch_bounds__(256) void loss_kernel(
    const int* __restrict__ y,
    const int* __restrict__ anchors,
    const int* __restrict__ sampled)
{
    __shared__ int   s_idx[SS];
    __shared__ int   s_y[SS];
    __shared__ float s_num[16], s_den[16], s_cnt[16];

    int a    = blockIdx.x;
    int tid  = threadIdx.x;
    int lane = tid & 31;
    int warp = tid >> 5;     // 0..7
    int hw   = lane >> 4;    // half-warp id (0/1)
    int hl   = lane & 15;    // lane within half-warp

    // Stage sample indices AND labels (random 4B gathers batched here with
    // 256 threads of MLP, out of the hot loop).
    for (int i = tid; i < SS; i += 256) {
        int si = sampled[(size_t)a * SS + i];
        s_idx[i] = si;
        s_y[i]   = y[si];
    }

    int ai = anchors[a];
    int ay = y[ai];

    // Anchor row: 8 fp16 per half-lane (float4 = 16B) -> 8 fp32 registers
    float af[8];
    {
        float4 ar = reinterpret_cast<const float4*>(g_xh + (size_t)ai * DD)[hl];
        const __half2* ah = reinterpret_cast<const __half2*>(&ar);
#pragma unroll
        for (int j = 0; j < 4; j++) {
            float2 f = __half22float2(ah[j]);
            af[2 * j]     = f.x;
            af[2 * j + 1] = f.y;
        }
    }
    __syncthreads();

    const int off = warp * 2 + hw;           // this half-warp's sample slot
    float num = 0.0f, den = 0.0f, cnt = 0.0f;

    // Ring of 3 prefetched sample fragments (each half-lane: 16 B = 8 fp16)
    float4 buf[3];
#pragma unroll
    for (int p = 0; p < 3; p++) {
        int si = s_idx[p * 16 + off];
        buf[p] = reinterpret_cast<const float4*>(g_xh + (size_t)si * DD)[hl];
    }

#pragma unroll
    for (int i = 0; i < 32; i++) {           // 32 samples per half-warp
        float4 cur = buf[i % 3];
        if (i + 3 < 32) {
            int si = s_idx[(i + 3) * 16 + off];
            buf[i % 3] = reinterpret_cast<const float4*>(g_xh + (size_t)si * DD)[hl];
        }
        const __half2* sh = reinterpret_cast<const __half2*>(&cur);
        float d = 0.0f;
#pragma unroll
        for (int j = 0; j < 4; j++) {
            float2 f = __half22float2(sh[j]);
            d = fmaf(af[2 * j],     f.x, d);
            d = fmaf(af[2 * j + 1], f.y, d);
        }
        // 16-lane reduce (xor offsets < 16 stay within the half-warp)
#pragma unroll
        for (int o = 8; o; o >>= 1) d += __shfl_xor_sync(0xFFFFFFFFu, d, o);
        float e = __expf(d * 10.0f);
        den += e;
        if (s_y[i * 16 + off] == ay) { num += e; cnt += 1.0f; }
    }

    if (hl == 0) { s_num[off] = num; s_den[off] = den; s_cnt[off] = cnt; }
    __syncthreads();

    if (tid == 0) {
        float nm = 0.0f, dn = 0.0f, c = 0.0f;
#pragma unroll
        for (int k = 0; k < 16; k++) { nm += s_num[k]; dn += s_den[k]; c += s_cnt[k]; }
        float loss = 0.0f;
        if (c > 0.0f) loss = (logf(dn) - logf(nm)) / c;  // -log(num/den)/cnt
        g_aloss[a] = loss;
    }
}

// ---------------------------------------------------------------------------
// Kernel 3: deterministic reduction of per-anchor losses.
// ---------------------------------------------------------------------------
__global__ void reduce_kernel(float* __restrict__ out) {
    __shared__ float sh[256];
    float s = 0.0f;
    for (int i = threadIdx.x; i < AA; i += 256) s += g_aloss[i];
    sh[threadIdx.x] = s;
    __syncthreads();
    for (int o = 128; o; o >>= 1) {
        if (threadIdx.x < o) sh[threadIdx.x] += sh[threadIdx.x + o];
        __syncthreads();
    }
    if (threadIdx.x == 0) out[0] = sh[0];
}

extern "C" void kernel_launch(void* const* d_in, const int* in_sizes, int n_in,
                              void* d_out, int out_size) {
    const float* x       = (const float*)d_in[0];
    const int*   y       = (const int*)  d_in[1];
    const int*   anchors = (const int*)  d_in[2];
    const int*   sampled = (const int*)  d_in[3];
    float*       out     = (float*)d_out;

    (void)in_sizes; (void)n_in; (void)out_size;

    norm_convert_kernel<<<(NN + 7) / 8, 256>>>(x);
    loss_kernel<<<AA, 256>>>(y, anchors, sampled);
    reduce_kernel<<<1, 256>>>(out);
}

// round 7
// speedup vs baseline: 2.2504x; 1.0364x over previous
#include <cuda_runtime.h>
#include <cuda_fp16.h>
#include <math.h>

#define NN 100000
#define DD 128
#define AA 4096
#define SS 512
// 1/TEMP = 10

// Scratch (no device mallocs allowed)
__device__ __half g_xh[(size_t)NN * DD];   // normalized fp16 features, 25.6 MB
__device__ float  g_aloss[AA];

// ---------------------------------------------------------------------------
// Kernel 1: fused normalize + fp16 convert. TWO rows per warp:
//  - both float4 loads issued back-to-back (MLP=2 per warp, better DRAM util)
//  - two independent shuffle-reduce chains interleave in the issue slots
//  - __ldcs: x is read exactly once -> evict-first, keep L2 for g_xh
// ---------------------------------------------------------------------------
__global__ void norm_convert_kernel(const float* __restrict__ x) {
    int warp = (blockIdx.x * blockDim.x + threadIdx.x) >> 5;
    int lane = threadIdx.x & 31;
    int r0 = warp * 2;
    int r1 = r0 + 1;
    if (r0 >= NN) return;

    float4 v0 = __ldcs(reinterpret_cast<const float4*>(x + (size_t)r0 * DD) + lane);
    bool has1 = (r1 < NN);
    float4 v1 = has1
        ? __ldcs(reinterpret_cast<const float4*>(x + (size_t)r1 * DD) + lane)
        : make_float4(0.f, 0.f, 0.f, 0.f);

    float s0 = v0.x * v0.x + v0.y * v0.y + v0.z * v0.z + v0.w * v0.w;
    float s1 = v1.x * v1.x + v1.y * v1.y + v1.z * v1.z + v1.w * v1.w;
#pragma unroll
    for (int o = 16; o; o >>= 1) {
        s0 += __shfl_xor_sync(0xFFFFFFFFu, s0, o);
        s1 += __shfl_xor_sync(0xFFFFFFFFu, s1, o);
    }
    float i0 = rsqrtf(s0);
    float i1 = rsqrtf(s1);

    __half2 h0[2], h1[2];
    h0[0] = __floats2half2_rn(v0.x * i0, v0.y * i0);
    h0[1] = __floats2half2_rn(v0.z * i0, v0.w * i0);
    reinterpret_cast<uint2*>(g_xh + (size_t)r0 * DD)[lane] =
        *reinterpret_cast<uint2*>(h0);
    if (has1) {
        h1[0] = __floats2half2_rn(v1.x * i1, v1.y * i1);
        h1[1] = __floats2half2_rn(v1.z * i1, v1.w * i1);
        reinterpret_cast<uint2*>(g_xh + (size_t)r1 * DD)[lane] =
            *reinterpret_cast<uint2*>(h1);
    }
}

// ---------------------------------------------------------------------------
// Kernel 2: one block (8 warps) per anchor. Half-warp per sample:
// each half-lane owns float4 = 16 B = 8 fp16 -> 16 lanes x 16 B = full 256 B
// row, coalesced. 3-deep software-pipelined prefetch ring keeps 3 LDGs in
// flight per half-warp, hiding L2 latency behind the convert/FMA/shuffle/exp
// chain of earlier samples. (At ~92% of LTS cap — do not touch.)
// ---------------------------------------------------------------------------
__global__ __launch_bounds__(256) void loss_kernel(
    const int* __restrict__ y,
    const int* __restrict__ anchors,
    const int* __restrict__ sampled)
{
    __shared__ int   s_idx[SS];
    __shared__ int   s_y[SS];
    __shared__ float s_num[16], s_den[16], s_cnt[16];

    int a    = blockIdx.x;
    int tid  = threadIdx.x;
    int lane = tid & 31;
    int warp = tid >> 5;     // 0..7
    int hw   = lane >> 4;    // half-warp id (0/1)
    int hl   = lane & 15;    // lane within half-warp

    // Stage sample indices AND labels (random 4B gathers batched here with
    // 256 threads of MLP, out of the hot loop).
    for (int i = tid; i < SS; i += 256) {
        int si = sampled[(size_t)a * SS + i];
        s_idx[i] = si;
        s_y[i]   = y[si];
    }

    int ai = anchors[a];
    int ay = y[ai];

    // Anchor row: 8 fp16 per half-lane (float4 = 16B) -> 8 fp32 registers
    float af[8];
    {
        float4 ar = reinterpret_cast<const float4*>(g_xh + (size_t)ai * DD)[hl];
        const __half2* ah = reinterpret_cast<const __half2*>(&ar);
#pragma unroll
        for (int j = 0; j < 4; j++) {
            float2 f = __half22float2(ah[j]);
            af[2 * j]     = f.x;
            af[2 * j + 1] = f.y;
        }
    }
    __syncthreads();

    const int off = warp * 2 + hw;           // this half-warp's sample slot
    float num = 0.0f, den = 0.0f, cnt = 0.0f;

    // Ring of 3 prefetched sample fragments (each half-lane: 16 B = 8 fp16)
    float4 buf[3];
#pragma unroll
    for (int p = 0; p < 3; p++) {
        int si = s_idx[p * 16 + off];
        buf[p] = reinterpret_cast<const float4*>(g_xh + (size_t)si * DD)[hl];
    }

#pragma unroll
    for (int i = 0; i < 32; i++) {           // 32 samples per half-warp
        float4 cur = buf[i % 3];
        if (i + 3 < 32) {
            int si = s_idx[(i + 3) * 16 + off];
            buf[i % 3] = reinterpret_cast<const float4*>(g_xh + (size_t)si * DD)[hl];
        }
        const __half2* sh = reinterpret_cast<const __half2*>(&cur);
        float d = 0.0f;
#pragma unroll
        for (int j = 0; j < 4; j++) {
            float2 f = __half22float2(sh[j]);
            d = fmaf(af[2 * j],     f.x, d);
            d = fmaf(af[2 * j + 1], f.y, d);
        }
        // 16-lane reduce (xor offsets < 16 stay within the half-warp)
#pragma unroll
        for (int o = 8; o; o >>= 1) d += __shfl_xor_sync(0xFFFFFFFFu, d, o);
        float e = __expf(d * 10.0f);
        den += e;
        if (s_y[i * 16 + off] == ay) { num += e; cnt += 1.0f; }
    }

    if (hl == 0) { s_num[off] = num; s_den[off] = den; s_cnt[off] = cnt; }
    __syncthreads();

    if (tid == 0) {
        float nm = 0.0f, dn = 0.0f, c = 0.0f;
#pragma unroll
        for (int k = 0; k < 16; k++) { nm += s_num[k]; dn += s_den[k]; c += s_cnt[k]; }
        float loss = 0.0f;
        if (c > 0.0f) loss = (logf(dn) - logf(nm)) / c;  // -log(num/den)/cnt
        g_aloss[a] = loss;
    }
}

// ---------------------------------------------------------------------------
// Kernel 3: deterministic reduction of per-anchor losses.
// ---------------------------------------------------------------------------
__global__ void reduce_kernel(float* __restrict__ out) {
    __shared__ float sh[256];
    float s = 0.0f;
    for (int i = threadIdx.x; i < AA; i += 256) s += g_aloss[i];
    sh[threadIdx.x] = s;
    __syncthreads();
    for (int o = 128; o; o >>= 1) {
        if (threadIdx.x < o) sh[threadIdx.x] += sh[threadIdx.x + o];
        __syncthreads();
    }
    if (threadIdx.x == 0) out[0] = sh[0];
}

extern "C" void kernel_launch(void* const* d_in, const int* in_sizes, int n_in,
                              void* d_out, int out_size) {
    const float* x       = (const float*)d_in[0];
    const int*   y       = (const int*)  d_in[1];
    const int*   anchors = (const int*)  d_in[2];
    const int*   sampled = (const int*)  d_in[3];
    float*       out     = (float*)d_out;

    (void)in_sizes; (void)n_in; (void)out_size;

    // 2 rows per warp -> 16 rows per 256-thread block
    norm_convert_kernel<<<(NN + 15) / 16, 256>>>(x);
    loss_kernel<<<AA, 256>>>(y, anchors, sampled);
    reduce_kernel<<<1, 256>>>(out);
}